// round 1
// baseline (speedup 1.0000x reference)
#include <cuda_runtime.h>
#include <cuda_bf16.h>
#include <mma.h>

using namespace nvcuda;

#define BB 16
#define CC 2048
#define HWN 4096
#define PD 128
#define AD 64
#define SS 64

// ---------------- device scratch (no allocations allowed) ----------------
__device__ float g_sum[PD];
__device__ float g_sumsq[PD];
__device__ float g_mean[PD];
__device__ float g_istd[PD];
__device__ int   g_idx[BB*SS];
__device__ float g_hs[BB*SS*(PD+AD)];   // 192 raw dot-products per sampled pixel
__device__ float g_tf[BB*SS*PD];
__device__ float g_tw[BB*SS];
__device__ float g_loss[BB];

// ---------------- init: zero accumulators ----------------
__global__ void k_init() {
    int i = blockIdx.x*blockDim.x + threadIdx.x;
    if (i < PD) { g_sum[i] = 0.f; g_sumsq[i] = 0.f; }
    if (i < BB*SS) g_idx[i] = 0;
    if (i < BB*SS*(PD+AD)) g_hs[i] = 0.f;
}

// ---------------- select: first 64 indices where label==1 (per image) ----------------
// Handles both int64 and int32 label storage (jax may downcast without x64).
__global__ void k_select(const int* __restrict__ L) {
    const int b = blockIdx.x;
    const int lane = threadIdx.x;
    // Probe odd int32 words within the first 65536 words (valid for both layouts).
    // int64 layout -> high words are all zero. int32 layout -> random 0/1 labels.
    int probe = 0;
    #pragma unroll
    for (int i = lane; i < 64; i += 32) probe |= L[2*(i*512)+1];
    unsigned any = __ballot_sync(0xffffffffu, probe != 0);
    const bool is64 = (any == 0u);
    const long long* L64 = (const long long*)L;

    int base = 0;
    for (int c = 0; c < 128; c++) {
        if (base >= 64) break;
        int p = (c << 5) + lane;
        long long v = is64 ? L64[(size_t)b*HWN + p] : (long long)L[(size_t)b*HWN + p];
        bool valid = (v == 1);
        unsigned m = __ballot_sync(0xffffffffu, valid);
        int pre = __popc(m & ((1u << lane) - 1u));
        if (valid && base + pre < 64) g_idx[b*64 + base + pre] = p;
        base += __popc(m);
    }
}

// ---------------- big conv1 + BN stats (bf16 WMMA, fp32 accum, no h materialization) --------
#define PIXP 136   // smem ld for A (pixels), bf16, padded
#define KP   40    // smem ld for B (k),      bf16, padded
#define CLD  132   // smem ld for C tile, fp32

__global__ __launch_bounds__(256) void k_conv1(const float* __restrict__ feats,
                                               const float* __restrict__ W1) {
    extern __shared__ char smraw[];
    __nv_bfloat16* Asb[2] = { (__nv_bfloat16*)(smraw),
                              (__nv_bfloat16*)(smraw + 18944) };
    __nv_bfloat16* Wsb[2] = { (__nv_bfloat16*)(smraw + 8704),
                              (__nv_bfloat16*)(smraw + 27648) };
    float* Cs = (float*)smraw;   // 128 x 132 fp32, reused after mainloop

    const int tid = threadIdx.x;
    const int b  = blockIdx.y;
    const int p0 = blockIdx.x * 128;
    const float* F = feats + (size_t)b*CC*HWN + p0;

    const int wid = tid >> 5;
    const int wr  = wid & 1;    // pixel half   (64 rows)
    const int wc  = wid >> 1;   // channel quarter (32 cols)

    wmma::fragment<wmma::accumulator,16,16,16,float> acc[4][2];
    #pragma unroll
    for (int i = 0; i < 4; i++)
        #pragma unroll
        for (int j = 0; j < 2; j++) wmma::fill_fragment(acc[i][j], 0.f);

    float4 ra[4], rw[4];
    auto loadG = [&](int kc) {
        #pragma unroll
        for (int i = 0; i < 4; i++) {
            int idx = tid + i*256;
            int k = idx >> 5, pq = idx & 31;
            ra[i] = *reinterpret_cast<const float4*>(F + (size_t)((kc<<5)+k)*HWN + (pq<<2));
        }
        #pragma unroll
        for (int i = 0; i < 4; i++) {
            int idx = tid + i*256;
            int ch = idx >> 3, kq = idx & 7;
            rw[i] = *reinterpret_cast<const float4*>(W1 + ch*CC + (kc<<5) + (kq<<2));
        }
    };
    auto storeS = [&](int buf) {
        __nv_bfloat16* A = Asb[buf];
        __nv_bfloat16* W = Wsb[buf];
        #pragma unroll
        for (int i = 0; i < 4; i++) {
            int idx = tid + i*256;
            int k = idx >> 5, pq = idx & 31;
            __nv_bfloat162* d = reinterpret_cast<__nv_bfloat162*>(A + k*PIXP + (pq<<2));
            d[0] = __floats2bfloat162_rn(ra[i].x, ra[i].y);
            d[1] = __floats2bfloat162_rn(ra[i].z, ra[i].w);
        }
        #pragma unroll
        for (int i = 0; i < 4; i++) {
            int idx = tid + i*256;
            int ch = idx >> 3, kq = idx & 7;
            __nv_bfloat162* d = reinterpret_cast<__nv_bfloat162*>(W + ch*KP + (kq<<2));
            d[0] = __floats2bfloat162_rn(rw[i].x, rw[i].y);
            d[1] = __floats2bfloat162_rn(rw[i].z, rw[i].w);
        }
    };

    loadG(0); storeS(0); __syncthreads();

    for (int kc = 0; kc < 64; kc++) {
        if (kc < 63) loadG(kc + 1);      // prefetch next chunk into registers
        const __nv_bfloat16* Ab = Asb[kc & 1];
        const __nv_bfloat16* Wb = Wsb[kc & 1];
        #pragma unroll
        for (int ks = 0; ks < 32; ks += 16) {
            wmma::fragment<wmma::matrix_a,16,16,16,__nv_bfloat16,wmma::col_major> af[4];
            #pragma unroll
            for (int i = 0; i < 4; i++)
                wmma::load_matrix_sync(af[i], Ab + ks*PIXP + wr*64 + i*16, PIXP);
            wmma::fragment<wmma::matrix_b,16,16,16,__nv_bfloat16,wmma::col_major> bf[2];
            #pragma unroll
            for (int j = 0; j < 2; j++)
                wmma::load_matrix_sync(bf[j], Wb + (wc*32 + j*16)*KP + ks, KP);
            #pragma unroll
            for (int i = 0; i < 4; i++)
                #pragma unroll
                for (int j = 0; j < 2; j++)
                    wmma::mma_sync(acc[i][j], af[i], bf[j], acc[i][j]);
        }
        __syncthreads();
        if (kc < 63) { storeS((kc + 1) & 1); __syncthreads(); }
    }

    // Epilogue: stash C tile to smem, reduce sum/sumsq over pixels per channel.
    #pragma unroll
    for (int i = 0; i < 4; i++)
        #pragma unroll
        for (int j = 0; j < 2; j++)
            wmma::store_matrix_sync(Cs + (wr*64 + i*16)*CLD + wc*32 + j*16,
                                    acc[i][j], CLD, wmma::mem_row_major);
    __syncthreads();
    if (tid < 128) {
        float s = 0.f, s2 = 0.f;
        #pragma unroll 4
        for (int p = 0; p < 128; p++) {
            float v = Cs[p*CLD + tid];
            s += v; s2 += v*v;
        }
        atomicAdd(&g_sum[tid], s);
        atomicAdd(&g_sumsq[tid], s2);
    }
}

// ---------------- finalize BN stats ----------------
__global__ void k_finstats(const float* __restrict__ b1) {
    int t = threadIdx.x;
    const float P = 65536.f;
    float m   = g_sum[t] / P;
    float var = g_sumsq[t] / P - m*m;   // shift-invariant: bias cancels in var
    g_mean[t] = m + b1[t];
    g_istd[t] = rsqrtf(var + 1e-5f);
}

// ---------------- sampled conv1 + attn-hidden, exact fp32 (K split across blocks) -------
__global__ __launch_bounds__(256) void k_sampled(const float* __restrict__ feats,
                                                 const float* __restrict__ W1,
                                                 const float* __restrict__ Wa1) {
    __shared__ float Fs[64][33];
    __shared__ float Ws[192][33];
    __shared__ int pix[64];
    const int tid = threadIdx.x;
    const int b = blockIdx.x;
    const int kbase = blockIdx.y * 256;
    if (tid < 64) pix[tid] = g_idx[b*64 + tid];

    float acc[4][12];
    #pragma unroll
    for (int i = 0; i < 4; i++)
        #pragma unroll
        for (int j = 0; j < 12; j++) acc[i][j] = 0.f;

    const int pg = tid & 15;   // pixel group:   4 pixels each
    const int cg = tid >> 4;   // channel group: 12 channels each
    const size_t fb = (size_t)b*CC*HWN;

    for (int chn = 0; chn < 8; chn++) {
        int k0 = kbase + chn*32;
        __syncthreads();
        #pragma unroll
        for (int i = 0; i < 8; i++) {
            int idx = tid + i*256;
            int px = idx >> 5, kk = idx & 31;
            Fs[px][kk] = feats[fb + (size_t)(k0+kk)*HWN + pix[px]];
        }
        #pragma unroll
        for (int i = 0; i < 24; i++) {
            int idx = tid + i*256;
            int r = idx >> 5, kk = idx & 31;
            Ws[r][kk] = (r < 128) ? W1[r*CC + k0 + kk] : Wa1[(r-128)*CC + k0 + kk];
        }
        __syncthreads();
        #pragma unroll 4
        for (int kk = 0; kk < 32; kk++) {
            float fv[4];
            #pragma unroll
            for (int i = 0; i < 4; i++) fv[i] = Fs[pg*4 + i][kk];
            #pragma unroll
            for (int j = 0; j < 12; j++) {
                float w = Ws[cg*12 + j][kk];
                #pragma unroll
                for (int i = 0; i < 4; i++) acc[i][j] += fv[i]*w;
            }
        }
    }
    #pragma unroll
    for (int i = 0; i < 4; i++)
        #pragma unroll
        for (int j = 0; j < 12; j++)
            atomicAdd(&g_hs[(b*64 + pg*4 + i)*192 + cg*12 + j], acc[i][j]);
}

// ---------------- per-pixel: BN apply + ReLU + conv2 + normalize + attention -------------
__global__ void k_proj(const float* __restrict__ b1, const float* __restrict__ gamma,
                       const float* __restrict__ beta, const float* __restrict__ W2,
                       const float* __restrict__ b2,  const float* __restrict__ ba1,
                       const float* __restrict__ Wa2, const float* __restrict__ ba2) {
    __shared__ float xr[128];
    __shared__ float ar[64];
    __shared__ float red[128];
    const int t = threadIdx.x;
    const int pid = blockIdx.x;
    const float* hb = g_hs + pid*192;
    {
        float h  = hb[t] + b1[t];
        float xn = (h - g_mean[t]) * g_istd[t] * gamma[t] + beta[t];
        xr[t] = fmaxf(xn, 0.f);
    }
    if (t < 64) ar[t] = fmaxf(hb[128+t] + ba1[t], 0.f);
    __syncthreads();

    float acc = b2[t];
    #pragma unroll 8
    for (int k = 0; k < 128; k++) acc += W2[t*128 + k] * xr[k];

    red[t] = acc*acc;
    __syncthreads();
    for (int s = 64; s > 0; s >>= 1) { if (t < s) red[t] += red[t+s]; __syncthreads(); }
    float rinv = 1.f / fmaxf(sqrtf(red[0]), 1e-12f);
    g_tf[pid*128 + t] = acc * rinv;

    if (t < 32) {
        float z = Wa2[t]*ar[t] + Wa2[t+32]*ar[t+32];
        #pragma unroll
        for (int o = 16; o > 0; o >>= 1) z += __shfl_down_sync(0xffffffffu, z, o);
        if (t == 0) g_tw[pid] = 1.f / (1.f + expf(-(z + ba2[0])));
    }
}

// ---------------- per-image contrastive loss ----------------
__global__ __launch_bounds__(256) void k_loss() {
    extern __shared__ float sm[];
    float* tfs   = sm;            // 64*128 = 8192
    float* tws   = sm + 8192;     // 64
    float* simM  = sm + 8256;     // 64*65 = 4160 (padded vs bank conflicts)
    float* denom = sm + 12416;    // 64
    float* red   = sm + 12480;    // 256
    const int t = threadIdx.x;
    const int b = blockIdx.x;

    for (int i = t; i < 8192; i += 256) tfs[i] = g_tf[b*8192 + i];
    if (t < 64) tws[t] = g_tw[b*64 + t];
    __syncthreads();

    const int i  = t >> 2;
    const int j0 = (t & 3) << 4;
    float acc[16];
    #pragma unroll
    for (int j = 0; j < 16; j++) acc[j] = 0.f;
    const float4* fi = reinterpret_cast<const float4*>(tfs + i*128);
    #pragma unroll 4
    for (int k4 = 0; k4 < 32; k4++) {
        float4 a = fi[k4];
        #pragma unroll
        for (int j = 0; j < 16; j++) {
            float4 c = reinterpret_cast<const float4*>(tfs + (j0 + j)*128)[k4];
            acc[j] += a.x*c.x + a.y*c.y + a.z*c.z + a.w*c.w;
        }
    }
    #pragma unroll
    for (int j = 0; j < 16; j++) simM[i*65 + j0 + j] = acc[j] / 0.1f;
    __syncthreads();

    if (t < 64) {
        float d = 0.f;
        for (int j = 0; j < 64; j++) d += expf(simM[t*65 + j]);
        denom[t] = d;
    }
    __syncthreads();

    float lacc = 0.f;
    float di = denom[i];
    float twi = tws[i];
    #pragma unroll
    for (int j = 0; j < 16; j++) {
        int jj = j0 + j;
        float s = simM[i*65 + jj];
        if (s > 0.7f && jj != i) {
            float lp = logf(expf(s)/di + 1e-10f);
            lacc += twi * tws[jj] * lp;
        }
    }
    red[t] = lacc;
    __syncthreads();
    for (int sft = 128; sft > 0; sft >>= 1) { if (t < sft) red[t] += red[t+sft]; __syncthreads(); }
    if (t == 0) {
        float tsum = 0.f;
        for (int j = 0; j < 64; j++) tsum += tws[j];
        g_loss[b] = -(0.1f/0.07f) * red[0] / tsum;
    }
}

// ---------------- final mean * LOSS_WEIGHT ----------------
__global__ void k_final(float* out) {
    int t = threadIdx.x;
    float v = (t < 16) ? g_loss[t] : 0.f;
    #pragma unroll
    for (int o = 16; o > 0; o >>= 1) v += __shfl_down_sync(0xffffffffu, v, o);
    if (t == 0) out[0] = (v / 16.0f) * 0.1f;
}

// ---------------- launch ----------------
extern "C" void kernel_launch(void* const* d_in, const int* in_sizes, int n_in,
                              void* d_out, int out_size) {
    const float* feats = (const float*)d_in[0];
    const int*   labels= (const int*)d_in[1];
    const float* W1   = (const float*)d_in[2];
    const float* b1   = (const float*)d_in[3];
    const float* gamma= (const float*)d_in[4];
    const float* beta = (const float*)d_in[5];
    const float* W2   = (const float*)d_in[6];
    const float* b2   = (const float*)d_in[7];
    const float* Wa1  = (const float*)d_in[8];
    const float* ba1  = (const float*)d_in[9];
    const float* Wa2  = (const float*)d_in[10];
    const float* ba2  = (const float*)d_in[11];

    cudaFuncSetAttribute(k_conv1, cudaFuncAttributeMaxDynamicSharedMemorySize, 69632);
    cudaFuncSetAttribute(k_loss,  cudaFuncAttributeMaxDynamicSharedMemorySize, 53248);

    k_init<<<768, 256>>>();
    k_select<<<16, 32>>>(labels);
    k_conv1<<<dim3(32, 16), 256, 67584>>>(feats, W1);
    k_finstats<<<1, 128>>>(b1);
    k_sampled<<<dim3(16, 8), 256>>>(feats, W1, Wa1);
    k_proj<<<1024, 128>>>(b1, gamma, beta, W2, b2, ba1, Wa2, ba2);
    k_loss<<<16, 256, 50944>>>();
    k_final<<<1, 32>>>((float*)d_out);
}